// round 14
// baseline (speedup 1.0000x reference)
#include <cuda_runtime.h>
#include <cuda_fp16.h>
#include <math.h>
#include <stdint.h>

#define NQ     22500
#define GRID_H 150
#define GRID_W 150

// ---------------- scratch (no allocations allowed) ----------------
// Aqc columns: [hi(q) 0..255 | hi(q+p) 256..511]
__device__ __half g_Aqc [NQ * 512];
__device__ __half g_S16 [NQ * 256];     // fp16(S)
__device__ __half g_V16 [NQ * 256];     // fp16 value (sampler input)
__device__ __half g_OFF [NQ * 128];     // fp16 offsets
__device__ __half g_ATT [NQ * 64];      // fp16 attn logits
__device__ __half g_Wv  [256 * 256];
__device__ __half g_Wcat[512 * 256];    // [W_off(0..127) | W_attn(128..191) | zero pad]
__device__ __half g_Wout[256 * 256];

// ---------------- helpers ----------------
__device__ __forceinline__ uint32_t smem_u32(const void* p) {
    return (uint32_t)__cvta_generic_to_shared(p);
}
__device__ __forceinline__ void ldsm_x4(uint32_t* r, uint32_t addr) {
    asm volatile("ldmatrix.sync.aligned.m8n8.x4.shared.b16 {%0,%1,%2,%3}, [%4];"
                 : "=r"(r[0]), "=r"(r[1]), "=r"(r[2]), "=r"(r[3]) : "r"(addr));
}
__device__ __forceinline__ void ldsm_x4_t(uint32_t* r, uint32_t addr) {
    asm volatile("ldmatrix.sync.aligned.m8n8.x4.trans.shared.b16 {%0,%1,%2,%3}, [%4];"
                 : "=r"(r[0]), "=r"(r[1]), "=r"(r[2]), "=r"(r[3]) : "r"(addr));
}
__device__ __forceinline__ void mma_f16(float* c, const uint32_t* a, const uint32_t* b) {
    asm volatile(
        "mma.sync.aligned.m16n8k16.row.col.f32.f16.f16.f32 "
        "{%0,%1,%2,%3}, {%4,%5,%6,%7}, {%8,%9}, {%0,%1,%2,%3};"
        : "+f"(c[0]), "+f"(c[1]), "+f"(c[2]), "+f"(c[3])
        : "r"(a[0]), "r"(a[1]), "r"(a[2]), "r"(a[3]), "r"(b[0]), "r"(b[1]));
}
__device__ __forceinline__ void cp16(void* smem, const void* gmem, bool pred) {
    int sz = pred ? 16 : 0;
    asm volatile("cp.async.cg.shared.global [%0], [%1], 16, %2;"
                 :: "r"(smem_u32(smem)), "l"(gmem), "r"(sz) : "memory");
}
__device__ __forceinline__ void cp_commit() {
    asm volatile("cp.async.commit_group;" ::: "memory");
}
template<int N> __device__ __forceinline__ void cp_wait() {
    asm volatile("cp.async.wait_group %0;" :: "n"(N) : "memory");
}
__device__ __forceinline__ uint2 hi4h(float4 v) {
    __half2 h0 = __floats2half2_rn(v.x, v.y);
    __half2 h1 = __floats2half2_rn(v.z, v.w);
    uint2 r; r.x = *(uint32_t*)&h0; r.y = *(uint32_t*)&h1; return r;
}

// ---------------- merged split kernel ----------------
// blocks [0,224): weight conversion; blocks [224, 224+5625): qcat convert
__global__ void __launch_bounds__(256) split_all(
    const float* __restrict__ q,   const float* __restrict__ qp,
    const float* __restrict__ Wv,  const float* __restrict__ Woff,
    const float* __restrict__ Watt,const float* __restrict__ Wout)
{
    int b = blockIdx.x;
    if (b < 224) {
        int idx = b * 256 + threadIdx.x;   // 57344 float4 slots
        const float* src; __half* dst; int N, ldd, coff, e;
        if      (idx < 16384) { src = Wv;   dst = g_Wv;   N = 256; ldd = 256; coff = 0;   e = idx;         }
        else if (idx < 32768) { src = Woff; dst = g_Wcat; N = 128; ldd = 256; coff = 0;   e = idx - 16384; }
        else if (idx < 40960) { src = Watt; dst = g_Wcat; N = 64;  ldd = 256; coff = 128; e = idx - 32768; }
        else                  { src = Wout; dst = g_Wout; N = 256; ldd = 256; coff = 0;   e = idx - 40960; }
        int n4 = N / 4;
        int k = e / n4;
        int n = (e % n4) * 4;
        float4 v = *(const float4*)(src + (size_t)k * N + n);
        *(uint2*)&dst[(size_t)k * ldd + coff + n] = hi4h(v);
    } else {
        int idx = (b - 224) * 256 + threadIdx.x;   // NQ*64
        int m = idx >> 6;
        int c = (idx & 63) * 4;
        float4 qv = *(const float4*)(q  + (size_t)m * 256 + c);
        float4 pv = *(const float4*)(qp + (size_t)m * 256 + c);
        float4 sv = make_float4(qv.x + pv.x, qv.y + pv.y, qv.z + pv.z, qv.w + pv.w);
        *(uint2*)&g_Aqc[(size_t)m * 512 + c]       = hi4h(qv);
        *(uint2*)&g_Aqc[(size_t)m * 512 + 256 + c] = hi4h(sv);
    }
}

// ----------------------------------------------------------------------------
// fp16 mma.sync GEMM, 128x128 tile, BK=64, 3-stage cp.async ring (96KB smem).
// 8 warps (4m x 2n); warp tile 32x64 (2 m-tiles x 8 n-tiles).
// MODE 0: fused — y 0 = OFF (cat cols 0..127, T=8), y 1 = ATT (cat 128..191 of
//         padded 256, T=8), y 2..3 = value (K=256, T=4). All fp16 out.
// MODE 1: output GEMM, K=256 (+bias +identity, fp32 out), y 0..1.
// ----------------------------------------------------------------------------
#define STAGE_BYTES 32768   // A 16KB + B 16KB
template<int MODE>
__global__ void __launch_bounds__(256, 2) mma_gemm(
    const __half* __restrict__ A, int lda,
    const __half* __restrict__ B0, const __half* __restrict__ B1,
    const float* __restrict__ bias0, const float* __restrict__ bias1,
    const float* __restrict__ bias2, const float* __restrict__ ident,
    float* __restrict__ D0, __half* __restrict__ H0,
    __half* __restrict__ H1, __half* __restrict__ H2,
    int M)
{
    extern __shared__ __align__(128) char smem[];

    const int tid  = threadIdx.x;
    const int lane = tid & 31;
    const int warp = tid >> 5;
    const int warp_m = warp & 3;
    const int warp_n = warp >> 2;
    const int m0 = blockIdx.x * 128;
    const int y  = blockIdx.y;

    // per-block uniform config
    const __half* Bp; int n0, T;
    if (MODE == 0) {
        if (y < 2) { n0 = y * 128; Bp = B1; T = 8; }          // cat (OFF/ATT)
        else       { n0 = (y - 2) * 128; Bp = B0; T = 4; }    // value
    } else {
        n0 = y * 128; Bp = B0; T = 4;
    }

    float c[2][8][4] = {};

    auto Abase = [&](int s) -> char* { return smem + s * STAGE_BYTES; };
    auto Bbase = [&](int s) -> char* { return smem + s * STAGE_BYTES + 16384; };

    auto issue = [&](int t, int s) {
        int ac = t * 64;
        char* Ab = Abase(s);
        #pragma unroll
        for (int i = 0; i < 4; i++) {          // A: 128 rows x 8 16B chunks
            int idx = i * 256 + tid;
            int r = idx >> 3, u = idx & 7;
            int m = m0 + r;
            const void* src = A + (size_t)(m < M ? m : M - 1) * lda + ac + u * 8;
            cp16(Ab + r * 128 + ((u ^ (r & 7)) << 4), src, m < M);
        }
        char* Bb = Bbase(s);
        #pragma unroll
        for (int i = 0; i < 4; i++) {          // B: 64 k-rows x 16 16B chunks
            int idx = i * 256 + tid;
            int r = idx >> 4, u = idx & 15;
            const void* src = Bp + (size_t)(t * 64 + r) * 256 + n0 + u * 8;
            cp16(Bb + r * 256 + ((u ^ (r & 7)) << 4), src, true);
        }
        cp_commit();
    };

    const int a_r = (lane & 7) + ((lane >> 3) & 1) * 8;
    const int a_u = (lane >> 4) & 1;
    const int b_r = (lane & 7) + ((lane >> 3) & 1) * 8;
    const int b_u = (lane >> 4) & 1;

    issue(0, 0);
    issue(1, 1);
    for (int t = 0; t < T; t++) {
        if (t + 1 < T) cp_wait<1>(); else cp_wait<0>();
        __syncthreads();                       // retires readers of buf (t-1)%3
        if (t + 2 < T) issue(t + 2, (t + 2) % 3);
        const char* Ab = Abase(t % 3);
        const char* Bb = Bbase(t % 3);
        #pragma unroll
        for (int k16 = 0; k16 < 4; k16++) {
            uint32_t a[2][4];
            #pragma unroll
            for (int mt = 0; mt < 2; mt++) {
                int r = warp_m * 32 + mt * 16 + a_r;
                int u = k16 * 2 + a_u;
                ldsm_x4(a[mt], smem_u32(Ab + r * 128 + ((u ^ (r & 7)) << 4)));
            }
            uint32_t b[8][2];
            #pragma unroll
            for (int ntp = 0; ntp < 4; ntp++) {
                int kr = k16 * 16 + b_r;
                int u  = warp_n * 8 + ntp * 2 + b_u;
                uint32_t rr[4];
                ldsm_x4_t(rr, smem_u32(Bb + kr * 256 + ((u ^ (kr & 7)) << 4)));
                b[ntp * 2][0] = rr[0];     b[ntp * 2][1] = rr[1];
                b[ntp * 2 + 1][0] = rr[2]; b[ntp * 2 + 1][1] = rr[3];
            }
            #pragma unroll
            for (int nt = 0; nt < 8; nt++)
                #pragma unroll
                for (int mt = 0; mt < 2; mt++)
                    mma_f16(c[mt][nt], a[mt], b[nt]);
        }
    }

    // ---- epilogue ----
    const int gid = lane >> 2, tig = lane & 3;
    #pragma unroll
    for (int mt = 0; mt < 2; mt++) {
        #pragma unroll
        for (int nt = 0; nt < 8; nt++) {
            int g = n0 + warp_n * 64 + nt * 8 + tig * 2;   // global output column
            // resolve destination
            __half* dh = nullptr; const float* bsp; int ldc_, col; bool ok = true;
            if (MODE == 0) {
                if (y == 0)      { dh = H1; bsp = bias1; ldc_ = 128; col = g; }
                else if (y == 1) {
                    if (g < 192) { dh = H2; bsp = bias2; ldc_ = 64; col = g - 128; }
                    else ok = false;
                } else           { dh = H0; bsp = bias0; ldc_ = 256; col = g; }
            } else {
                bsp = bias0; ldc_ = 256; col = g;
            }
            if (!ok) continue;
            float b0 = bsp[col], b1 = bsp[col + 1];
            int r0 = m0 + warp_m * 32 + mt * 16 + gid;
            if (r0 < M) {
                float2 o = make_float2(c[mt][nt][0] + b0, c[mt][nt][1] + b1);
                if (MODE == 1) {
                    float2 id = *(const float2*)(ident + (size_t)r0 * 256 + col);
                    o.x += id.x; o.y += id.y;
                    *(float2*)(D0 + (size_t)r0 * 256 + col) = o;
                } else {
                    __half2 oh = __floats2half2_rn(o.x, o.y);
                    *(uint32_t*)(dh + (size_t)r0 * ldc_ + col) = *(uint32_t*)&oh;
                }
            }
            int r1 = r0 + 8;
            if (r1 < M) {
                float2 o = make_float2(c[mt][nt][2] + b0, c[mt][nt][3] + b1);
                if (MODE == 1) {
                    float2 id = *(const float2*)(ident + (size_t)r1 * 256 + col);
                    o.x += id.x; o.y += id.y;
                    *(float2*)(D0 + (size_t)r1 * 256 + col) = o;
                } else {
                    __half2 oh = __floats2half2_rn(o.x, o.y);
                    *(uint32_t*)(dh + (size_t)r1 * ldc_ + col) = *(uint32_t*)&oh;
                }
            }
        }
    }
}

// ----------------------------------------------------------------------------
// Deformable sampling: 32 threads/query (8 heads x 4 groups), 8 channels/thread.
// All inputs fp16 (V, OFF, ATT); fp32 accumulation; fp16 S out.
// ----------------------------------------------------------------------------
__global__ void __launch_bounds__(256) sample_kernel(
    const __half* __restrict__ V, const __half* __restrict__ OFF,
    const __half* __restrict__ ATT, const float* __restrict__ RP)
{
    const int q = blockIdx.x * 8 + (threadIdx.x >> 5);
    if (q >= NQ) return;
    const int lane = threadIdx.x & 31;
    const int h    = lane >> 2;
    const int ch0  = h * 32 + (lane & 3) * 8;

    uint4 attv = *(const uint4*)(ATT + (size_t)q * 64 + h * 8);
    uint4 offv[2];
    offv[0] = *(const uint4*)(OFF + (size_t)q * 128 + h * 16);
    offv[1] = *(const uint4*)(OFF + (size_t)q * 128 + h * 16 + 8);
    const __half2* ap = (const __half2*)&attv;

    float4 acc0 = make_float4(0.f, 0.f, 0.f, 0.f);
    float4 acc1 = make_float4(0.f, 0.f, 0.f, 0.f);
    #pragma unroll
    for (int qu = 0; qu < 2; qu++) {
        float2 a01 = __half22float2(ap[qu * 2 + 0]);
        float2 a23 = __half22float2(ap[qu * 2 + 1]);
        float l0 = a01.x, l1 = a01.y, l2 = a23.x, l3 = a23.y;
        float mx = fmaxf(fmaxf(l0, l1), fmaxf(l2, l3));
        float e0 = __expf(l0 - mx), e1 = __expf(l1 - mx);
        float e2 = __expf(l2 - mx), e3 = __expf(l3 - mx);
        float inv = 1.f / (e0 + e1 + e2 + e3);
        float w[4] = {e0 * inv, e1 * inv, e2 * inv, e3 * inv};

        float rpx = RP[(size_t)qu * NQ * 2 + (size_t)q * 2 + 0];
        float rpy = RP[(size_t)qu * NQ * 2 + (size_t)q * 2 + 1];
        const __half2* op = (const __half2*)&offv[qu];

        #pragma unroll
        for (int p = 0; p < 4; p++) {
            float2 oxy = __half22float2(op[p]);
            float x = (rpx + oxy.x * (1.f / GRID_W)) * GRID_W - 0.5f;
            float y = (rpy + oxy.y * (1.f / GRID_H)) * GRID_H - 0.5f;
            float x0f = floorf(x), y0f = floorf(y);
            float wx = x - x0f, wy = y - y0f;
            int x0 = (int)x0f, y0 = (int)y0f;
            float aw = w[p];
            float tw[4] = {aw * (1.f - wx) * (1.f - wy), aw * wx * (1.f - wy),
                           aw * (1.f - wx) * wy,          aw * wx * wy};
            int xs[4] = {x0, x0 + 1, x0,     x0 + 1};
            int ys[4] = {y0, y0,     y0 + 1, y0 + 1};
            #pragma unroll
            for (int t = 0; t < 4; t++) {
                int xx = xs[t], yy = ys[t];
                if (xx >= 0 && xx < GRID_W && yy >= 0 && yy < GRID_H) {
                    uint4 rv = __ldg((const uint4*)(V +
                        ((size_t)yy * GRID_W + xx) * 256 + ch0));
                    const __half2* hp = (const __half2*)&rv;
                    float2 f0 = __half22float2(hp[0]);
                    float2 f1 = __half22float2(hp[1]);
                    float2 f2 = __half22float2(hp[2]);
                    float2 f3 = __half22float2(hp[3]);
                    float wt = tw[t];
                    acc0.x += f0.x * wt; acc0.y += f0.y * wt;
                    acc0.z += f1.x * wt; acc0.w += f1.y * wt;
                    acc1.x += f2.x * wt; acc1.y += f2.y * wt;
                    acc1.z += f3.x * wt; acc1.w += f3.y * wt;
                }
            }
        }
    }
    acc0.x *= 0.5f; acc0.y *= 0.5f; acc0.z *= 0.5f; acc0.w *= 0.5f;
    acc1.x *= 0.5f; acc1.y *= 0.5f; acc1.z *= 0.5f; acc1.w *= 0.5f;
    __half* Sq = g_S16 + (size_t)q * 256;
    *(uint2*)&Sq[ch0]     = hi4h(acc0);
    *(uint2*)&Sq[ch0 + 4] = hi4h(acc1);
}

// ----------------------------------------------------------------------------
extern "C" void kernel_launch(void* const* d_in, const int* in_sizes, int n_in,
                              void* d_out, int out_size)
{
    const float* query  = (const float*)d_in[0];
    const float* qpos   = (const float*)d_in[1];
    const float* rp     = (const float*)d_in[2];
    const float* W_off  = (const float*)d_in[3];
    const float* b_off  = (const float*)d_in[4];
    const float* W_attn = (const float*)d_in[5];
    const float* b_attn = (const float*)d_in[6];
    const float* W_v    = (const float*)d_in[7];
    const float* b_v    = (const float*)d_in[8];
    const float* W_out  = (const float*)d_in[9];
    const float* b_out  = (const float*)d_in[10];
    float* out = (float*)d_out;

    __half *Aqc, *S16, *V16, *OFF, *ATT, *Wv, *Wcat, *Wout;
    cudaGetSymbolAddress((void**)&Aqc,  g_Aqc);
    cudaGetSymbolAddress((void**)&S16,  g_S16);
    cudaGetSymbolAddress((void**)&V16,  g_V16);
    cudaGetSymbolAddress((void**)&OFF,  g_OFF);
    cudaGetSymbolAddress((void**)&ATT,  g_ATT);
    cudaGetSymbolAddress((void**)&Wv,   g_Wv);
    cudaGetSymbolAddress((void**)&Wcat, g_Wcat);
    cudaGetSymbolAddress((void**)&Wout, g_Wout);

    const int SMEM = 3 * STAGE_BYTES;   // 98304
    cudaFuncSetAttribute(mma_gemm<0>, cudaFuncAttributeMaxDynamicSharedMemorySize, SMEM);
    cudaFuncSetAttribute(mma_gemm<1>, cudaFuncAttributeMaxDynamicSharedMemorySize, SMEM);

    const int MB = (NQ + 127) / 128;  // 176
    dim3 blk(256);

    // splits (weights + qcat) in one launch
    split_all<<<224 + NQ * 64 / 256, blk>>>(query, qpos, W_v, W_off, W_attn, W_out);

    // fused: y0 = OFF, y1 = ATT (cat, T=8, heavy-first), y2..3 = value (T=4)
    mma_gemm<0><<<dim3(MB, 4), blk, SMEM>>>(Aqc, 512, Wv, Wcat,
                                            b_v, b_off, b_attn, nullptr,
                                            nullptr, V16, OFF, ATT, NQ);
    // sampling (all fp16 inputs) -> fp16 S
    sample_kernel<<<(NQ + 7) / 8, blk>>>(V16, OFF, ATT, rp);

    // out = S @ W_out + b_out + query  (K=256, fp32 out)
    mma_gemm<1><<<dim3(MB, 2), blk, SMEM>>>(S16, 256, Wout, nullptr,
                                            b_out, nullptr, nullptr, query,
                                            out, nullptr, nullptr, nullptr, NQ);
}

// round 15
// speedup vs baseline: 1.0171x; 1.0171x over previous
#include <cuda_runtime.h>
#include <cuda_fp16.h>
#include <math.h>
#include <stdint.h>

#define NQ     22500
#define GRID_H 150
#define GRID_W 150

// ---------------- scratch (no allocations allowed) ----------------
// Aqc columns: [hi(q) 0..255 | hi(q+p) 256..511]
__device__ __half g_Aqc [NQ * 512];
__device__ __half g_S16 [NQ * 256];     // fp16(S)
__device__ __half g_V16 [NQ * 256];     // fp16 value (sampler input)
__device__ __half g_OFF [NQ * 128];     // fp16 offsets
__device__ __half g_ATT [NQ * 64];      // fp16 attn logits
__device__ __half g_Wv  [256 * 256];
__device__ __half g_Wcat[512 * 192];    // [W_off | W_attn]
__device__ __half g_Wout[256 * 256];

// ---------------- helpers ----------------
__device__ __forceinline__ uint32_t smem_u32(const void* p) {
    return (uint32_t)__cvta_generic_to_shared(p);
}
__device__ __forceinline__ void ldsm_x4(uint32_t* r, uint32_t addr) {
    asm volatile("ldmatrix.sync.aligned.m8n8.x4.shared.b16 {%0,%1,%2,%3}, [%4];"
                 : "=r"(r[0]), "=r"(r[1]), "=r"(r[2]), "=r"(r[3]) : "r"(addr));
}
__device__ __forceinline__ void ldsm_x4_t(uint32_t* r, uint32_t addr) {
    asm volatile("ldmatrix.sync.aligned.m8n8.x4.trans.shared.b16 {%0,%1,%2,%3}, [%4];"
                 : "=r"(r[0]), "=r"(r[1]), "=r"(r[2]), "=r"(r[3]) : "r"(addr));
}
__device__ __forceinline__ void mma_f16(float* c, const uint32_t* a, const uint32_t* b) {
    asm volatile(
        "mma.sync.aligned.m16n8k16.row.col.f32.f16.f16.f32 "
        "{%0,%1,%2,%3}, {%4,%5,%6,%7}, {%8,%9}, {%0,%1,%2,%3};"
        : "+f"(c[0]), "+f"(c[1]), "+f"(c[2]), "+f"(c[3])
        : "r"(a[0]), "r"(a[1]), "r"(a[2]), "r"(a[3]), "r"(b[0]), "r"(b[1]));
}
__device__ __forceinline__ void cp16(void* smem, const void* gmem, bool pred) {
    int sz = pred ? 16 : 0;
    asm volatile("cp.async.cg.shared.global [%0], [%1], 16, %2;"
                 :: "r"(smem_u32(smem)), "l"(gmem), "r"(sz) : "memory");
}
__device__ __forceinline__ void cp_commit() {
    asm volatile("cp.async.commit_group;" ::: "memory");
}
template<int N> __device__ __forceinline__ void cp_wait() {
    asm volatile("cp.async.wait_group %0;" :: "n"(N) : "memory");
}
__device__ __forceinline__ uint2 hi4h(float4 v) {
    __half2 h0 = __floats2half2_rn(v.x, v.y);
    __half2 h1 = __floats2half2_rn(v.z, v.w);
    uint2 r; r.x = *(uint32_t*)&h0; r.y = *(uint32_t*)&h1; return r;
}

// ---------------- merged split kernel ----------------
// blocks [0,224): weight conversion; blocks [224, 224+5625): qcat convert
__global__ void __launch_bounds__(256) split_all(
    const float* __restrict__ q,   const float* __restrict__ qp,
    const float* __restrict__ Wv,  const float* __restrict__ Woff,
    const float* __restrict__ Watt,const float* __restrict__ Wout)
{
    int b = blockIdx.x;
    if (b < 224) {
        int idx = b * 256 + threadIdx.x;   // 57344 float4 slots
        const float* src; __half* dst; int N, ldd, coff, e;
        if      (idx < 16384) { src = Wv;   dst = g_Wv;   N = 256; ldd = 256; coff = 0;   e = idx;         }
        else if (idx < 32768) { src = Woff; dst = g_Wcat; N = 128; ldd = 192; coff = 0;   e = idx - 16384; }
        else if (idx < 40960) { src = Watt; dst = g_Wcat; N = 64;  ldd = 192; coff = 128; e = idx - 32768; }
        else                  { src = Wout; dst = g_Wout; N = 256; ldd = 256; coff = 0;   e = idx - 40960; }
        int n4 = N / 4;
        int k = e / n4;
        int n = (e % n4) * 4;
        float4 v = *(const float4*)(src + (size_t)k * N + n);
        *(uint2*)&dst[(size_t)k * ldd + coff + n] = hi4h(v);
    } else {
        int idx = (b - 224) * 256 + threadIdx.x;   // NQ*64
        int m = idx >> 6;
        int c = (idx & 63) * 4;
        float4 qv = *(const float4*)(q  + (size_t)m * 256 + c);
        float4 pv = *(const float4*)(qp + (size_t)m * 256 + c);
        float4 sv = make_float4(qv.x + pv.x, qv.y + pv.y, qv.z + pv.z, qv.w + pv.w);
        *(uint2*)&g_Aqc[(size_t)m * 512 + c]       = hi4h(qv);
        *(uint2*)&g_Aqc[(size_t)m * 512 + 256 + c] = hi4h(sv);
    }
}

// ----------------------------------------------------------------------------
// fp16 mma.sync GEMM, BK=64, 128x64 tiles (R13 config).
// MODE 0: 3-stage cp.async ring; y 0..3 = value (K=256), 4..5 = OFF, 6 = ATT
//         (K=512); fp16 out.
// MODE 1: K=256 output GEMM. FULL PREFETCH: all 4 slabs issued upfront as
//         separate groups (96KB in flight), drained with cp_wait<3-t>. No
//         ring dependency, maximal MLP. (+bias +identity, fp32 out).
// ----------------------------------------------------------------------------
#define STAGE_BYTES 24576   // A 16KB + B 8KB
template<int MODE>
__global__ void __launch_bounds__(256) mma_gemm(
    const __half* __restrict__ A, int lda,
    const __half* __restrict__ B0, const __half* __restrict__ B1,
    const float* __restrict__ bias0, const float* __restrict__ bias1,
    const float* __restrict__ bias2, const float* __restrict__ ident,
    float* __restrict__ D0, __half* __restrict__ H0,
    __half* __restrict__ H1, __half* __restrict__ H2,
    int M)
{
    extern __shared__ __align__(128) char smem[];

    const int tid  = threadIdx.x;
    const int lane = tid & 31;
    const int warp = tid >> 5;
    const int warp_m = warp & 3;
    const int warp_n = warp >> 2;
    const int m0 = blockIdx.x * 128;

    // per-block uniform config
    const __half* Bp; int ldb, n0, T;
    __half* dsth = nullptr; const float* bs; int ldc, cbase;
    if (MODE == 0) {
        int y = blockIdx.y;
        if (y < 4) {
            n0 = y * 64; Bp = B0; ldb = 256; T = 4;
            dsth = H0; bs = bias0; ldc = 256; cbase = n0;
        } else {
            n0 = (y - 4) * 64; Bp = B1; ldb = 192; T = 8;
            if (y < 6) { dsth = H1; bs = bias1; ldc = 128; cbase = n0; }
            else       { dsth = H2; bs = bias2; ldc = 64;  cbase = 0;  }
        }
    } else {
        n0 = blockIdx.y * 64; Bp = B0; ldb = 256; T = 4;
        bs = bias0; ldc = 256; cbase = n0;
    }

    float c[2][4][4] = {};

    auto Abase = [&](int s) -> char* { return smem + s * STAGE_BYTES; };
    auto Bbase = [&](int s) -> char* { return smem + s * STAGE_BYTES + 16384; };

    auto issue = [&](int t, int s) {
        int ac = t * 64;
        char* Ab = Abase(s);
        #pragma unroll
        for (int i = 0; i < 4; i++) {          // A: 128 rows x 8 16B chunks
            int idx = i * 256 + tid;
            int r = idx >> 3, u = idx & 7;
            int m = m0 + r;
            const void* src = A + (size_t)(m < M ? m : M - 1) * lda + ac + u * 8;
            cp16(Ab + r * 128 + ((u ^ (r & 7)) << 4), src, m < M);
        }
        char* Bb = Bbase(s);
        #pragma unroll
        for (int i = 0; i < 2; i++) {          // B: 64 rows x 8 chunks
            int idx = i * 256 + tid;
            int r = idx >> 3, u = idx & 7;
            const void* src = Bp + (size_t)(t * 64 + r) * ldb + n0 + u * 8;
            cp16(Bb + r * 128 + ((u ^ (r & 7)) << 4), src, true);
        }
        cp_commit();
    };

    const int a_r = (lane & 7) + ((lane >> 3) & 1) * 8;
    const int a_u = (lane >> 4) & 1;
    const int b_r = (lane & 7) + ((lane >> 3) & 1) * 8;
    const int b_u = (lane >> 4) & 1;

    auto compute_slab = [&](const char* Ab, const char* Bb) {
        #pragma unroll
        for (int k16 = 0; k16 < 4; k16++) {
            uint32_t a[2][4];
            #pragma unroll
            for (int mt = 0; mt < 2; mt++) {
                int r = warp_m * 32 + mt * 16 + a_r;
                int u = k16 * 2 + a_u;
                ldsm_x4(a[mt], smem_u32(Ab + r * 128 + ((u ^ (r & 7)) << 4)));
            }
            uint32_t b[4][2];
            #pragma unroll
            for (int ntp = 0; ntp < 2; ntp++) {
                int kr = k16 * 16 + b_r;
                int u  = warp_n * 4 + ntp * 2 + b_u;
                uint32_t rr[4];
                ldsm_x4_t(rr, smem_u32(Bb + kr * 128 + ((u ^ (kr & 7)) << 4)));
                b[ntp * 2][0] = rr[0];     b[ntp * 2][1] = rr[1];
                b[ntp * 2 + 1][0] = rr[2]; b[ntp * 2 + 1][1] = rr[3];
            }
            #pragma unroll
            for (int nt = 0; nt < 4; nt++)
                #pragma unroll
                for (int mt = 0; mt < 2; mt++)
                    mma_f16(c[mt][nt], a[mt], b[nt]);
        }
    };

    if (MODE == 1) {
        // full prefetch: 4 slabs = whole K, 96KB in flight, no ring deps
        issue(0, 0); issue(1, 1); issue(2, 2); issue(3, 3);
        cp_wait<3>(); __syncthreads(); compute_slab(Abase(0), Bbase(0));
        cp_wait<2>(); __syncthreads(); compute_slab(Abase(1), Bbase(1));
        cp_wait<1>(); __syncthreads(); compute_slab(Abase(2), Bbase(2));
        cp_wait<0>(); __syncthreads(); compute_slab(Abase(3), Bbase(3));
    } else {
        issue(0, 0);
        issue(1, 1);
        for (int t = 0; t < T; t++) {
            if (t + 1 < T) cp_wait<1>(); else cp_wait<0>();
            __syncthreads();                   // retires readers of buf (t-1)%3
            if (t + 2 < T) issue(t + 2, (t + 2) % 3);
            compute_slab(Abase(t % 3), Bbase(t % 3));
            // NOTE: ring reuse is safe because the next issue for this buffer
            // happens only after the barrier two iterations later.
            if (t + 2 < T) { /* buffer (t+2)%3 refilled above */ }
            __syncthreads();
        }
    }

    // ---- epilogue ----
    const int gid = lane >> 2, tig = lane & 3;
    #pragma unroll
    for (int mt = 0; mt < 2; mt++) {
        #pragma unroll
        for (int nt = 0; nt < 4; nt++) {
            int cc = cbase + warp_n * 32 + nt * 8 + tig * 2;
            float b0 = bs[cc], b1 = bs[cc + 1];
            int r0 = m0 + warp_m * 32 + mt * 16 + gid;
            if (r0 < M) {
                float2 o = make_float2(c[mt][nt][0] + b0, c[mt][nt][1] + b1);
                if (MODE == 1) {
                    float2 id = *(const float2*)(ident + (size_t)r0 * ldc + cc);
                    o.x += id.x; o.y += id.y;
                    *(float2*)(D0 + (size_t)r0 * ldc + cc) = o;
                } else {
                    __half2 oh = __floats2half2_rn(o.x, o.y);
                    *(uint32_t*)(dsth + (size_t)r0 * ldc + cc) = *(uint32_t*)&oh;
                }
            }
            int r1 = r0 + 8;
            if (r1 < M) {
                float2 o = make_float2(c[mt][nt][2] + b0, c[mt][nt][3] + b1);
                if (MODE == 1) {
                    float2 id = *(const float2*)(ident + (size_t)r1 * ldc + cc);
                    o.x += id.x; o.y += id.y;
                    *(float2*)(D0 + (size_t)r1 * ldc + cc) = o;
                } else {
                    __half2 oh = __floats2half2_rn(o.x, o.y);
                    *(uint32_t*)(dsth + (size_t)r1 * ldc + cc) = *(uint32_t*)&oh;
                }
            }
        }
    }
}

// ----------------------------------------------------------------------------
// Deformable sampling: 32 threads/query (8 heads x 4 groups), 8 channels/thread.
// All inputs fp16 (V, OFF, ATT); fp32 accumulation; fp16 S out.
// ----------------------------------------------------------------------------
__global__ void __launch_bounds__(256) sample_kernel(
    const __half* __restrict__ V, const __half* __restrict__ OFF,
    const __half* __restrict__ ATT, const float* __restrict__ RP)
{
    const int q = blockIdx.x * 8 + (threadIdx.x >> 5);
    if (q >= NQ) return;
    const int lane = threadIdx.x & 31;
    const int h    = lane >> 2;
    const int ch0  = h * 32 + (lane & 3) * 8;

    uint4 attv = *(const uint4*)(ATT + (size_t)q * 64 + h * 8);
    uint4 offv[2];
    offv[0] = *(const uint4*)(OFF + (size_t)q * 128 + h * 16);
    offv[1] = *(const uint4*)(OFF + (size_t)q * 128 + h * 16 + 8);
    const __half2* ap = (const __half2*)&attv;

    float4 acc0 = make_float4(0.f, 0.f, 0.f, 0.f);
    float4 acc1 = make_float4(0.f, 0.f, 0.f, 0.f);
    #pragma unroll
    for (int qu = 0; qu < 2; qu++) {
        float2 a01 = __half22float2(ap[qu * 2 + 0]);
        float2 a23 = __half22float2(ap[qu * 2 + 1]);
        float l0 = a01.x, l1 = a01.y, l2 = a23.x, l3 = a23.y;
        float mx = fmaxf(fmaxf(l0, l1), fmaxf(l2, l3));
        float e0 = __expf(l0 - mx), e1 = __expf(l1 - mx);
        float e2 = __expf(l2 - mx), e3 = __expf(l3 - mx);
        float inv = 1.f / (e0 + e1 + e2 + e3);
        float w[4] = {e0 * inv, e1 * inv, e2 * inv, e3 * inv};

        float rpx = RP[(size_t)qu * NQ * 2 + (size_t)q * 2 + 0];
        float rpy = RP[(size_t)qu * NQ * 2 + (size_t)q * 2 + 1];
        const __half2* op = (const __half2*)&offv[qu];

        #pragma unroll
        for (int p = 0; p < 4; p++) {
            float2 oxy = __half22float2(op[p]);
            float x = (rpx + oxy.x * (1.f / GRID_W)) * GRID_W - 0.5f;
            float y = (rpy + oxy.y * (1.f / GRID_H)) * GRID_H - 0.5f;
            float x0f = floorf(x), y0f = floorf(y);
            float wx = x - x0f, wy = y - y0f;
            int x0 = (int)x0f, y0 = (int)y0f;
            float aw = w[p];
            float tw[4] = {aw * (1.f - wx) * (1.f - wy), aw * wx * (1.f - wy),
                           aw * (1.f - wx) * wy,          aw * wx * wy};
            int xs[4] = {x0, x0 + 1, x0,     x0 + 1};
            int ys[4] = {y0, y0,     y0 + 1, y0 + 1};
            #pragma unroll
            for (int t = 0; t < 4; t++) {
                int xx = xs[t], yy = ys[t];
                if (xx >= 0 && xx < GRID_W && yy >= 0 && yy < GRID_H) {
                    uint4 rv = __ldg((const uint4*)(V +
                        ((size_t)yy * GRID_W + xx) * 256 + ch0));
                    const __half2* hp = (const __half2*)&rv;
                    float2 f0 = __half22float2(hp[0]);
                    float2 f1 = __half22float2(hp[1]);
                    float2 f2 = __half22float2(hp[2]);
                    float2 f3 = __half22float2(hp[3]);
                    float wt = tw[t];
                    acc0.x += f0.x * wt; acc0.y += f0.y * wt;
                    acc0.z += f1.x * wt; acc0.w += f1.y * wt;
                    acc1.x += f2.x * wt; acc1.y += f2.y * wt;
                    acc1.z += f3.x * wt; acc1.w += f3.y * wt;
                }
            }
        }
    }
    acc0.x *= 0.5f; acc0.y *= 0.5f; acc0.z *= 0.5f; acc0.w *= 0.5f;
    acc1.x *= 0.5f; acc1.y *= 0.5f; acc1.z *= 0.5f; acc1.w *= 0.5f;
    __half* Sq = g_S16 + (size_t)q * 256;
    *(uint2*)&Sq[ch0]     = hi4h(acc0);
    *(uint2*)&Sq[ch0 + 4] = hi4h(acc1);
}

// ----------------------------------------------------------------------------
extern "C" void kernel_launch(void* const* d_in, const int* in_sizes, int n_in,
                              void* d_out, int out_size)
{
    const float* query  = (const float*)d_in[0];
    const float* qpos   = (const float*)d_in[1];
    const float* rp     = (const float*)d_in[2];
    const float* W_off  = (const float*)d_in[3];
    const float* b_off  = (const float*)d_in[4];
    const float* W_attn = (const float*)d_in[5];
    const float* b_attn = (const float*)d_in[6];
    const float* W_v    = (const float*)d_in[7];
    const float* b_v    = (const float*)d_in[8];
    const float* W_out  = (const float*)d_in[9];
    const float* b_out  = (const float*)d_in[10];
    float* out = (float*)d_out;

    __half *Aqc, *S16, *V16, *OFF, *ATT, *Wv, *Wcat, *Wout;
    cudaGetSymbolAddress((void**)&Aqc,  g_Aqc);
    cudaGetSymbolAddress((void**)&S16,  g_S16);
    cudaGetSymbolAddress((void**)&V16,  g_V16);
    cudaGetSymbolAddress((void**)&OFF,  g_OFF);
    cudaGetSymbolAddress((void**)&ATT,  g_ATT);
    cudaGetSymbolAddress((void**)&Wv,   g_Wv);
    cudaGetSymbolAddress((void**)&Wcat, g_Wcat);
    cudaGetSymbolAddress((void**)&Wout, g_Wout);

    const int SMEM3 = 3 * STAGE_BYTES;   // 73728 (MODE 0 ring)
    const int SMEM4 = 4 * STAGE_BYTES;   // 98304 (MODE 1 full prefetch)
    cudaFuncSetAttribute(mma_gemm<0>, cudaFuncAttributeMaxDynamicSharedMemorySize, SMEM3);
    cudaFuncSetAttribute(mma_gemm<1>, cudaFuncAttributeMaxDynamicSharedMemorySize, SMEM4);

    const int MB = (NQ + 127) / 128;  // 176
    dim3 blk(256);

    // splits (weights + qcat) in one launch
    split_all<<<224 + NQ * 64 / 256, blk>>>(query, qpos, W_v, W_off, W_attn, W_out);

    // fused: value GEMM (y 0..3, K=256) + OFF (y 4..5) + ATT (y 6), all fp16 out
    mma_gemm<0><<<dim3(MB, 7), blk, SMEM3>>>(Aqc, 512, Wv, Wcat,
                                             b_v, b_off, b_attn, nullptr,
                                             nullptr, V16, OFF, ATT, NQ);
    // sampling (all fp16 inputs) -> fp16 S
    sample_kernel<<<(NQ + 7) / 8, blk>>>(V16, OFF, ATT, rp);

    // out = S @ W_out + b_out + query  (K=256, fp32 out, full-prefetch path)
    mma_gemm<1><<<dim3(MB, 4), blk, SMEM4>>>(S16, 256, Wout, nullptr,
                                             b_out, nullptr, nullptr, query,
                                             out, nullptr, nullptr, nullptr, NQ);
}

// round 16
// speedup vs baseline: 1.0475x; 1.0299x over previous
#include <cuda_runtime.h>
#include <cuda_fp16.h>
#include <math.h>
#include <stdint.h>

#define NQ     22500
#define GRID_H 150
#define GRID_W 150

// ---------------- scratch (no allocations allowed) ----------------
// Aqc columns: [hi(q) 0..255 | hi(q+p) 256..511]
__device__ __half g_Aqc [NQ * 512];
__device__ __half g_S16 [NQ * 256];     // fp16(S)
__device__ __half g_V16 [NQ * 256];     // fp16 value (sampler input)
__device__ __half g_OFF [NQ * 128];     // fp16 offsets
__device__ __half g_ATT [NQ * 64];      // fp16 attn logits
__device__ __half g_Wv  [256 * 256];
__device__ __half g_Wcat[512 * 192];    // [W_off | W_attn]
__device__ __half g_Wout[256 * 256];

// ---------------- helpers ----------------
__device__ __forceinline__ uint32_t smem_u32(const void* p) {
    return (uint32_t)__cvta_generic_to_shared(p);
}
__device__ __forceinline__ void ldsm_x4(uint32_t* r, uint32_t addr) {
    asm volatile("ldmatrix.sync.aligned.m8n8.x4.shared.b16 {%0,%1,%2,%3}, [%4];"
                 : "=r"(r[0]), "=r"(r[1]), "=r"(r[2]), "=r"(r[3]) : "r"(addr));
}
__device__ __forceinline__ void ldsm_x4_t(uint32_t* r, uint32_t addr) {
    asm volatile("ldmatrix.sync.aligned.m8n8.x4.trans.shared.b16 {%0,%1,%2,%3}, [%4];"
                 : "=r"(r[0]), "=r"(r[1]), "=r"(r[2]), "=r"(r[3]) : "r"(addr));
}
__device__ __forceinline__ void mma_f16(float* c, const uint32_t* a, const uint32_t* b) {
    asm volatile(
        "mma.sync.aligned.m16n8k16.row.col.f32.f16.f16.f32 "
        "{%0,%1,%2,%3}, {%4,%5,%6,%7}, {%8,%9}, {%0,%1,%2,%3};"
        : "+f"(c[0]), "+f"(c[1]), "+f"(c[2]), "+f"(c[3])
        : "r"(a[0]), "r"(a[1]), "r"(a[2]), "r"(a[3]), "r"(b[0]), "r"(b[1]));
}
__device__ __forceinline__ void cp16(void* smem, const void* gmem, bool pred) {
    int sz = pred ? 16 : 0;
    asm volatile("cp.async.cg.shared.global [%0], [%1], 16, %2;"
                 :: "r"(smem_u32(smem)), "l"(gmem), "r"(sz) : "memory");
}
__device__ __forceinline__ void cp_commit() {
    asm volatile("cp.async.commit_group;" ::: "memory");
}
template<int N> __device__ __forceinline__ void cp_wait() {
    asm volatile("cp.async.wait_group %0;" :: "n"(N) : "memory");
}
__device__ __forceinline__ uint2 hi4h(float4 v) {
    __half2 h0 = __floats2half2_rn(v.x, v.y);
    __half2 h1 = __floats2half2_rn(v.z, v.w);
    uint2 r; r.x = *(uint32_t*)&h0; r.y = *(uint32_t*)&h1; return r;
}

// ---------------- merged split kernel ----------------
// blocks [0,224): weight conversion; blocks [224, 224+5625): qcat convert
__global__ void __launch_bounds__(256) split_all(
    const float* __restrict__ q,   const float* __restrict__ qp,
    const float* __restrict__ Wv,  const float* __restrict__ Woff,
    const float* __restrict__ Watt,const float* __restrict__ Wout)
{
    int b = blockIdx.x;
    if (b < 224) {
        int idx = b * 256 + threadIdx.x;   // 57344 float4 slots
        const float* src; __half* dst; int N, ldd, coff, e;
        if      (idx < 16384) { src = Wv;   dst = g_Wv;   N = 256; ldd = 256; coff = 0;   e = idx;         }
        else if (idx < 32768) { src = Woff; dst = g_Wcat; N = 128; ldd = 192; coff = 0;   e = idx - 16384; }
        else if (idx < 40960) { src = Watt; dst = g_Wcat; N = 64;  ldd = 192; coff = 128; e = idx - 32768; }
        else                  { src = Wout; dst = g_Wout; N = 256; ldd = 256; coff = 0;   e = idx - 40960; }
        int n4 = N / 4;
        int k = e / n4;
        int n = (e % n4) * 4;
        float4 v = *(const float4*)(src + (size_t)k * N + n);
        *(uint2*)&dst[(size_t)k * ldd + coff + n] = hi4h(v);
    } else {
        int idx = (b - 224) * 256 + threadIdx.x;   // NQ*64
        int m = idx >> 6;
        int c = (idx & 63) * 4;
        float4 qv = *(const float4*)(q  + (size_t)m * 256 + c);
        float4 pv = *(const float4*)(qp + (size_t)m * 256 + c);
        float4 sv = make_float4(qv.x + pv.x, qv.y + pv.y, qv.z + pv.z, qv.w + pv.w);
        *(uint2*)&g_Aqc[(size_t)m * 512 + c]       = hi4h(qv);
        *(uint2*)&g_Aqc[(size_t)m * 512 + 256 + c] = hi4h(sv);
    }
}

// ----------------------------------------------------------------------------
// fp16 mma.sync GEMM, BK=64, 128x64 tiles, 2-stage 48KB ring -> 4 blocks/SM
// (32 warps resident; inter-block overlap hides slab latency).
// MODE 0: fused — y 0..1 = OFF, y 2 = ATT (K=512, heavy, scheduled first),
//         y 3..6 = value (K=256). All fp16 out.
// MODE 1: output GEMM, K=256 (+bias +identity, fp32 out).
// ----------------------------------------------------------------------------
#define STAGE_BYTES 24576   // A 16KB + B 8KB
template<int MODE>
__global__ void __launch_bounds__(256) mma_gemm(
    const __half* __restrict__ A, int lda,
    const __half* __restrict__ B0, const __half* __restrict__ B1,
    const float* __restrict__ bias0, const float* __restrict__ bias1,
    const float* __restrict__ bias2, const float* __restrict__ ident,
    float* __restrict__ D0, __half* __restrict__ H0,
    __half* __restrict__ H1, __half* __restrict__ H2,
    int M)
{
    extern __shared__ __align__(128) char smem[];

    const int tid  = threadIdx.x;
    const int lane = tid & 31;
    const int warp = tid >> 5;
    const int warp_m = warp & 3;
    const int warp_n = warp >> 2;
    const int m0 = blockIdx.x * 128;

    // per-block uniform config (heavy K=512 tiles at low y => scheduled first)
    const __half* Bp; int ldb, n0, T;
    __half* dsth = nullptr; const float* bs; int ldc, cbase;
    if (MODE == 0) {
        int y = blockIdx.y;
        if (y < 2)      { n0 = y * 64; Bp = B1; ldb = 192; T = 8;
                          dsth = H1; bs = bias1; ldc = 128; cbase = n0; }
        else if (y == 2){ n0 = 128;   Bp = B1; ldb = 192; T = 8;
                          dsth = H2; bs = bias2; ldc = 64;  cbase = 0;  }
        else            { n0 = (y - 3) * 64; Bp = B0; ldb = 256; T = 4;
                          dsth = H0; bs = bias0; ldc = 256; cbase = n0; }
    } else {
        n0 = blockIdx.y * 64; Bp = B0; ldb = 256; T = 4;
        bs = bias0; ldc = 256; cbase = n0;
    }

    float c[2][4][4] = {};

    auto Abase = [&](int s) -> char* { return smem + s * STAGE_BYTES; };
    auto Bbase = [&](int s) -> char* { return smem + s * STAGE_BYTES + 16384; };

    auto issue = [&](int t, int s) {
        int ac = t * 64;
        char* Ab = Abase(s);
        #pragma unroll
        for (int i = 0; i < 4; i++) {          // A: 128 rows x 8 16B chunks
            int idx = i * 256 + tid;
            int r = idx >> 3, u = idx & 7;
            int m = m0 + r;
            const void* src = A + (size_t)(m < M ? m : M - 1) * lda + ac + u * 8;
            cp16(Ab + r * 128 + ((u ^ (r & 7)) << 4), src, m < M);
        }
        char* Bb = Bbase(s);
        #pragma unroll
        for (int i = 0; i < 2; i++) {          // B: 64 rows x 8 chunks
            int idx = i * 256 + tid;
            int r = idx >> 3, u = idx & 7;
            const void* src = Bp + (size_t)(t * 64 + r) * ldb + n0 + u * 8;
            cp16(Bb + r * 128 + ((u ^ (r & 7)) << 4), src, true);
        }
        cp_commit();
    };

    const int a_r = (lane & 7) + ((lane >> 3) & 1) * 8;
    const int a_u = (lane >> 4) & 1;
    const int b_r = (lane & 7) + ((lane >> 3) & 1) * 8;
    const int b_u = (lane >> 4) & 1;

    auto compute_slab = [&](const char* Ab, const char* Bb) {
        #pragma unroll
        for (int k16 = 0; k16 < 4; k16++) {
            uint32_t a[2][4];
            #pragma unroll
            for (int mt = 0; mt < 2; mt++) {
                int r = warp_m * 32 + mt * 16 + a_r;
                int u = k16 * 2 + a_u;
                ldsm_x4(a[mt], smem_u32(Ab + r * 128 + ((u ^ (r & 7)) << 4)));
            }
            uint32_t b[4][2];
            #pragma unroll
            for (int ntp = 0; ntp < 2; ntp++) {
                int kr = k16 * 16 + b_r;
                int u  = warp_n * 4 + ntp * 2 + b_u;
                uint32_t rr[4];
                ldsm_x4_t(rr, smem_u32(Bb + kr * 128 + ((u ^ (kr & 7)) << 4)));
                b[ntp * 2][0] = rr[0];     b[ntp * 2][1] = rr[1];
                b[ntp * 2 + 1][0] = rr[2]; b[ntp * 2 + 1][1] = rr[3];
            }
            #pragma unroll
            for (int nt = 0; nt < 4; nt++)
                #pragma unroll
                for (int mt = 0; mt < 2; mt++)
                    mma_f16(c[mt][nt], a[mt], b[nt]);
        }
    };

    // 2-stage ring: compute slab t from buf t%2; refill that buf with t+2
    issue(0, 0);
    issue(1, 1);
    for (int t = 0; t < T; t++) {
        if (t + 1 < T) cp_wait<1>(); else cp_wait<0>();
        __syncthreads();
        compute_slab(Abase(t & 1), Bbase(t & 1));
        __syncthreads();
        if (t + 2 < T) issue(t + 2, t & 1);
    }

    // ---- epilogue ----
    const int gid = lane >> 2, tig = lane & 3;
    #pragma unroll
    for (int mt = 0; mt < 2; mt++) {
        #pragma unroll
        for (int nt = 0; nt < 4; nt++) {
            int cc = cbase + warp_n * 32 + nt * 8 + tig * 2;
            float b0 = bs[cc], b1 = bs[cc + 1];
            int r0 = m0 + warp_m * 32 + mt * 16 + gid;
            if (r0 < M) {
                float2 o = make_float2(c[mt][nt][0] + b0, c[mt][nt][1] + b1);
                if (MODE == 1) {
                    float2 id = *(const float2*)(ident + (size_t)r0 * ldc + cc);
                    o.x += id.x; o.y += id.y;
                    *(float2*)(D0 + (size_t)r0 * ldc + cc) = o;
                } else {
                    __half2 oh = __floats2half2_rn(o.x, o.y);
                    *(uint32_t*)(dsth + (size_t)r0 * ldc + cc) = *(uint32_t*)&oh;
                }
            }
            int r1 = r0 + 8;
            if (r1 < M) {
                float2 o = make_float2(c[mt][nt][2] + b0, c[mt][nt][3] + b1);
                if (MODE == 1) {
                    float2 id = *(const float2*)(ident + (size_t)r1 * ldc + cc);
                    o.x += id.x; o.y += id.y;
                    *(float2*)(D0 + (size_t)r1 * ldc + cc) = o;
                } else {
                    __half2 oh = __floats2half2_rn(o.x, o.y);
                    *(uint32_t*)(dsth + (size_t)r1 * ldc + cc) = *(uint32_t*)&oh;
                }
            }
        }
    }
}

// ----------------------------------------------------------------------------
// Deformable sampling: 32 threads/query (8 heads x 4 groups), 8 channels/thread.
// All inputs fp16 (V, OFF, ATT); fp32 accumulation; fp16 S out.
// ----------------------------------------------------------------------------
__global__ void __launch_bounds__(256) sample_kernel(
    const __half* __restrict__ V, const __half* __restrict__ OFF,
    const __half* __restrict__ ATT, const float* __restrict__ RP)
{
    const int q = blockIdx.x * 8 + (threadIdx.x >> 5);
    if (q >= NQ) return;
    const int lane = threadIdx.x & 31;
    const int h    = lane >> 2;
    const int ch0  = h * 32 + (lane & 3) * 8;

    uint4 attv = *(const uint4*)(ATT + (size_t)q * 64 + h * 8);
    uint4 offv[2];
    offv[0] = *(const uint4*)(OFF + (size_t)q * 128 + h * 16);
    offv[1] = *(const uint4*)(OFF + (size_t)q * 128 + h * 16 + 8);
    const __half2* ap = (const __half2*)&attv;

    float4 acc0 = make_float4(0.f, 0.f, 0.f, 0.f);
    float4 acc1 = make_float4(0.f, 0.f, 0.f, 0.f);
    #pragma unroll
    for (int qu = 0; qu < 2; qu++) {
        float2 a01 = __half22float2(ap[qu * 2 + 0]);
        float2 a23 = __half22float2(ap[qu * 2 + 1]);
        float l0 = a01.x, l1 = a01.y, l2 = a23.x, l3 = a23.y;
        float mx = fmaxf(fmaxf(l0, l1), fmaxf(l2, l3));
        float e0 = __expf(l0 - mx), e1 = __expf(l1 - mx);
        float e2 = __expf(l2 - mx), e3 = __expf(l3 - mx);
        float inv = 1.f / (e0 + e1 + e2 + e3);
        float w[4] = {e0 * inv, e1 * inv, e2 * inv, e3 * inv};

        float rpx = RP[(size_t)qu * NQ * 2 + (size_t)q * 2 + 0];
        float rpy = RP[(size_t)qu * NQ * 2 + (size_t)q * 2 + 1];
        const __half2* op = (const __half2*)&offv[qu];

        #pragma unroll
        for (int p = 0; p < 4; p++) {
            float2 oxy = __half22float2(op[p]);
            float x = (rpx + oxy.x * (1.f / GRID_W)) * GRID_W - 0.5f;
            float y = (rpy + oxy.y * (1.f / GRID_H)) * GRID_H - 0.5f;
            float x0f = floorf(x), y0f = floorf(y);
            float wx = x - x0f, wy = y - y0f;
            int x0 = (int)x0f, y0 = (int)y0f;
            float aw = w[p];
            float tw[4] = {aw * (1.f - wx) * (1.f - wy), aw * wx * (1.f - wy),
                           aw * (1.f - wx) * wy,          aw * wx * wy};
            int xs[4] = {x0, x0 + 1, x0,     x0 + 1};
            int ys[4] = {y0, y0,     y0 + 1, y0 + 1};
            #pragma unroll
            for (int t = 0; t < 4; t++) {
                int xx = xs[t], yy = ys[t];
                if (xx >= 0 && xx < GRID_W && yy >= 0 && yy < GRID_H) {
                    uint4 rv = __ldg((const uint4*)(V +
                        ((size_t)yy * GRID_W + xx) * 256 + ch0));
                    const __half2* hp = (const __half2*)&rv;
                    float2 f0 = __half22float2(hp[0]);
                    float2 f1 = __half22float2(hp[1]);
                    float2 f2 = __half22float2(hp[2]);
                    float2 f3 = __half22float2(hp[3]);
                    float wt = tw[t];
                    acc0.x += f0.x * wt; acc0.y += f0.y * wt;
                    acc0.z += f1.x * wt; acc0.w += f1.y * wt;
                    acc1.x += f2.x * wt; acc1.y += f2.y * wt;
                    acc1.z += f3.x * wt; acc1.w += f3.y * wt;
                }
            }
        }
    }
    acc0.x *= 0.5f; acc0.y *= 0.5f; acc0.z *= 0.5f; acc0.w *= 0.5f;
    acc1.x *= 0.5f; acc1.y *= 0.5f; acc1.z *= 0.5f; acc1.w *= 0.5f;
    __half* Sq = g_S16 + (size_t)q * 256;
    *(uint2*)&Sq[ch0]     = hi4h(acc0);
    *(uint2*)&Sq[ch0 + 4] = hi4h(acc1);
}

// ----------------------------------------------------------------------------
extern "C" void kernel_launch(void* const* d_in, const int* in_sizes, int n_in,
                              void* d_out, int out_size)
{
    const float* query  = (const float*)d_in[0];
    const float* qpos   = (const float*)d_in[1];
    const float* rp     = (const float*)d_in[2];
    const float* W_off  = (const float*)d_in[3];
    const float* b_off  = (const float*)d_in[4];
    const float* W_attn = (const float*)d_in[5];
    const float* b_attn = (const float*)d_in[6];
    const float* W_v    = (const float*)d_in[7];
    const float* b_v    = (const float*)d_in[8];
    const float* W_out  = (const float*)d_in[9];
    const float* b_out  = (const float*)d_in[10];
    float* out = (float*)d_out;

    __half *Aqc, *S16, *V16, *OFF, *ATT, *Wv, *Wcat, *Wout;
    cudaGetSymbolAddress((void**)&Aqc,  g_Aqc);
    cudaGetSymbolAddress((void**)&S16,  g_S16);
    cudaGetSymbolAddress((void**)&V16,  g_V16);
    cudaGetSymbolAddress((void**)&OFF,  g_OFF);
    cudaGetSymbolAddress((void**)&ATT,  g_ATT);
    cudaGetSymbolAddress((void**)&Wv,   g_Wv);
    cudaGetSymbolAddress((void**)&Wcat, g_Wcat);
    cudaGetSymbolAddress((void**)&Wout, g_Wout);

    const int SMEM = 2 * STAGE_BYTES;   // 49152 -> 4 blocks/SM
    cudaFuncSetAttribute(mma_gemm<0>, cudaFuncAttributeMaxDynamicSharedMemorySize, SMEM);
    cudaFuncSetAttribute(mma_gemm<1>, cudaFuncAttributeMaxDynamicSharedMemorySize, SMEM);

    const int MB = (NQ + 127) / 128;  // 176
    dim3 blk(256);

    // splits (weights + qcat) in one launch
    split_all<<<224 + NQ * 64 / 256, blk>>>(query, qpos, W_v, W_off, W_attn, W_out);

    // fused: y0..1 = OFF, y2 = ATT (K=512, heavy-first), y3..6 = value (K=256)
    mma_gemm<0><<<dim3(MB, 7), blk, SMEM>>>(Aqc, 512, Wv, Wcat,
                                            b_v, b_off, b_attn, nullptr,
                                            nullptr, V16, OFF, ATT, NQ);
    // sampling (all fp16 inputs) -> fp16 S
    sample_kernel<<<(NQ + 7) / 8, blk>>>(V16, OFF, ATT, rp);

    // out = S @ W_out + b_out + query  (K=256, fp32 out)
    mma_gemm<1><<<dim3(MB, 4), blk, SMEM>>>(S16, 256, Wout, nullptr,
                                            b_out, nullptr, nullptr, query,
                                            out, nullptr, nullptr, nullptr, NQ);
}

// round 17
// speedup vs baseline: 1.0615x; 1.0134x over previous
#include <cuda_runtime.h>
#include <cuda_fp16.h>
#include <math.h>
#include <stdint.h>

#define NQ     22500
#define GRID_H 150
#define GRID_W 150

// ---------------- scratch (no allocations allowed) ----------------
// Aqc columns: [hi(q) 0..255 | hi(q+p) 256..511]
__device__ __half g_Aqc [NQ * 512];
__device__ __half g_S16 [NQ * 256];     // fp16(S)
__device__ __half g_V16 [NQ * 256];     // fp16 value (sampler input)
__device__ __half g_OFF [NQ * 128];     // fp16 offsets
__device__ __half g_ATT [NQ * 64];      // fp16 attn logits
__device__ __half g_Wv  [256 * 256];
__device__ __half g_Wcat[512 * 192];    // [W_off | W_attn]
__device__ __half g_Wout[256 * 256];

// ---------------- helpers ----------------
__device__ __forceinline__ uint32_t smem_u32(const void* p) {
    return (uint32_t)__cvta_generic_to_shared(p);
}
__device__ __forceinline__ void ldsm_x4(uint32_t* r, uint32_t addr) {
    asm volatile("ldmatrix.sync.aligned.m8n8.x4.shared.b16 {%0,%1,%2,%3}, [%4];"
                 : "=r"(r[0]), "=r"(r[1]), "=r"(r[2]), "=r"(r[3]) : "r"(addr));
}
__device__ __forceinline__ void ldsm_x4_t(uint32_t* r, uint32_t addr) {
    asm volatile("ldmatrix.sync.aligned.m8n8.x4.trans.shared.b16 {%0,%1,%2,%3}, [%4];"
                 : "=r"(r[0]), "=r"(r[1]), "=r"(r[2]), "=r"(r[3]) : "r"(addr));
}
__device__ __forceinline__ void mma_f16(float* c, const uint32_t* a, const uint32_t* b) {
    asm volatile(
        "mma.sync.aligned.m16n8k16.row.col.f32.f16.f16.f32 "
        "{%0,%1,%2,%3}, {%4,%5,%6,%7}, {%8,%9}, {%0,%1,%2,%3};"
        : "+f"(c[0]), "+f"(c[1]), "+f"(c[2]), "+f"(c[3])
        : "r"(a[0]), "r"(a[1]), "r"(a[2]), "r"(a[3]), "r"(b[0]), "r"(b[1]));
}
__device__ __forceinline__ void cp16(void* smem, const void* gmem, bool pred) {
    int sz = pred ? 16 : 0;
    asm volatile("cp.async.cg.shared.global [%0], [%1], 16, %2;"
                 :: "r"(smem_u32(smem)), "l"(gmem), "r"(sz) : "memory");
}
__device__ __forceinline__ void cp_commit() {
    asm volatile("cp.async.commit_group;" ::: "memory");
}
template<int N> __device__ __forceinline__ void cp_wait() {
    asm volatile("cp.async.wait_group %0;" :: "n"(N) : "memory");
}
__device__ __forceinline__ uint2 hi4h(float4 v) {
    __half2 h0 = __floats2half2_rn(v.x, v.y);
    __half2 h1 = __floats2half2_rn(v.z, v.w);
    uint2 r; r.x = *(uint32_t*)&h0; r.y = *(uint32_t*)&h1; return r;
}

// ---------------- merged split kernel ----------------
// blocks [0,224): weight conversion; blocks [224, 224+5625): qcat convert
__global__ void __launch_bounds__(256) split_all(
    const float* __restrict__ q,   const float* __restrict__ qp,
    const float* __restrict__ Wv,  const float* __restrict__ Woff,
    const float* __restrict__ Watt,const float* __restrict__ Wout)
{
    int b = blockIdx.x;
    if (b < 224) {
        int idx = b * 256 + threadIdx.x;   // 57344 float4 slots
        const float* src; __half* dst; int N, ldd, coff, e;
        if      (idx < 16384) { src = Wv;   dst = g_Wv;   N = 256; ldd = 256; coff = 0;   e = idx;         }
        else if (idx < 32768) { src = Woff; dst = g_Wcat; N = 128; ldd = 192; coff = 0;   e = idx - 16384; }
        else if (idx < 40960) { src = Watt; dst = g_Wcat; N = 64;  ldd = 192; coff = 128; e = idx - 32768; }
        else                  { src = Wout; dst = g_Wout; N = 256; ldd = 256; coff = 0;   e = idx - 40960; }
        int n4 = N / 4;
        int k = e / n4;
        int n = (e % n4) * 4;
        float4 v = *(const float4*)(src + (size_t)k * N + n);
        *(uint2*)&dst[(size_t)k * ldd + coff + n] = hi4h(v);
    } else {
        int idx = (b - 224) * 256 + threadIdx.x;   // NQ*64
        int m = idx >> 6;
        int c = (idx & 63) * 4;
        float4 qv = *(const float4*)(q  + (size_t)m * 256 + c);
        float4 pv = *(const float4*)(qp + (size_t)m * 256 + c);
        float4 sv = make_float4(qv.x + pv.x, qv.y + pv.y, qv.z + pv.z, qv.w + pv.w);
        *(uint2*)&g_Aqc[(size_t)m * 512 + c]       = hi4h(qv);
        *(uint2*)&g_Aqc[(size_t)m * 512 + 256 + c] = hi4h(sv);
    }
}

// ----------------------------------------------------------------------------
// fp16 mma.sync GEMM, BK=64, 128x64 tiles, 2-stage 48KB ring.
// launch_bounds min-blocks forces the register ceiling so occupancy is real:
//   MODE 1 -> 4 blocks/SM (<=64 regs, proven achievable), MODE 0 -> 3 blocks.
// MODE 0: fused — y 0..1 = OFF, y 2 = ATT (K=512, heavy-first),
//         y 3..6 = value (K=256). All fp16 out.
// MODE 1: output GEMM, K=256 (+bias +identity, fp32 out).
// ----------------------------------------------------------------------------
#define STAGE_BYTES 24576   // A 16KB + B 8KB
template<int MODE>
__global__ void __launch_bounds__(256, MODE == 1 ? 4 : 3) mma_gemm(
    const __half* __restrict__ A, int lda,
    const __half* __restrict__ B0, const __half* __restrict__ B1,
    const float* __restrict__ bias0, const float* __restrict__ bias1,
    const float* __restrict__ bias2, const float* __restrict__ ident,
    float* __restrict__ D0, __half* __restrict__ H0,
    __half* __restrict__ H1, __half* __restrict__ H2,
    int M)
{
    extern __shared__ __align__(128) char smem[];

    const int tid  = threadIdx.x;
    const int lane = tid & 31;
    const int warp = tid >> 5;
    const int warp_m = warp & 3;
    const int warp_n = warp >> 2;
    const int m0 = blockIdx.x * 128;

    // per-block uniform config (heavy K=512 tiles at low y => scheduled first)
    const __half* Bp; int ldb, n0, T;
    __half* dsth = nullptr; const float* bs; int ldc, cbase;
    if (MODE == 0) {
        int y = blockIdx.y;
        if (y < 2)      { n0 = y * 64; Bp = B1; ldb = 192; T = 8;
                          dsth = H1; bs = bias1; ldc = 128; cbase = n0; }
        else if (y == 2){ n0 = 128;   Bp = B1; ldb = 192; T = 8;
                          dsth = H2; bs = bias2; ldc = 64;  cbase = 0;  }
        else            { n0 = (y - 3) * 64; Bp = B0; ldb = 256; T = 4;
                          dsth = H0; bs = bias0; ldc = 256; cbase = n0; }
    } else {
        n0 = blockIdx.y * 64; Bp = B0; ldb = 256; T = 4;
        bs = bias0; ldc = 256; cbase = n0;
    }

    float c[2][4][4] = {};

    auto Abase = [&](int s) -> char* { return smem + s * STAGE_BYTES; };
    auto Bbase = [&](int s) -> char* { return smem + s * STAGE_BYTES + 16384; };

    auto issue = [&](int t, int s) {
        int ac = t * 64;
        char* Ab = Abase(s);
        #pragma unroll
        for (int i = 0; i < 4; i++) {          // A: 128 rows x 8 16B chunks
            int idx = i * 256 + tid;
            int r = idx >> 3, u = idx & 7;
            int m = m0 + r;
            const void* src = A + (size_t)(m < M ? m : M - 1) * lda + ac + u * 8;
            cp16(Ab + r * 128 + ((u ^ (r & 7)) << 4), src, m < M);
        }
        char* Bb = Bbase(s);
        #pragma unroll
        for (int i = 0; i < 2; i++) {          // B: 64 rows x 8 chunks
            int idx = i * 256 + tid;
            int r = idx >> 3, u = idx & 7;
            const void* src = Bp + (size_t)(t * 64 + r) * ldb + n0 + u * 8;
            cp16(Bb + r * 128 + ((u ^ (r & 7)) << 4), src, true);
        }
        cp_commit();
    };

    const int a_r = (lane & 7) + ((lane >> 3) & 1) * 8;
    const int a_u = (lane >> 4) & 1;
    const int b_r = (lane & 7) + ((lane >> 3) & 1) * 8;
    const int b_u = (lane >> 4) & 1;

    auto compute_slab = [&](const char* Ab, const char* Bb) {
        #pragma unroll
        for (int k16 = 0; k16 < 4; k16++) {
            uint32_t a[2][4];
            #pragma unroll
            for (int mt = 0; mt < 2; mt++) {
                int r = warp_m * 32 + mt * 16 + a_r;
                int u = k16 * 2 + a_u;
                ldsm_x4(a[mt], smem_u32(Ab + r * 128 + ((u ^ (r & 7)) << 4)));
            }
            uint32_t b[4][2];
            #pragma unroll
            for (int ntp = 0; ntp < 2; ntp++) {
                int kr = k16 * 16 + b_r;
                int u  = warp_n * 4 + ntp * 2 + b_u;
                uint32_t rr[4];
                ldsm_x4_t(rr, smem_u32(Bb + kr * 128 + ((u ^ (kr & 7)) << 4)));
                b[ntp * 2][0] = rr[0];     b[ntp * 2][1] = rr[1];
                b[ntp * 2 + 1][0] = rr[2]; b[ntp * 2 + 1][1] = rr[3];
            }
            #pragma unroll
            for (int nt = 0; nt < 4; nt++)
                #pragma unroll
                for (int mt = 0; mt < 2; mt++)
                    mma_f16(c[mt][nt], a[mt], b[nt]);
        }
    };

    // 2-stage ring: compute slab t from buf t%2; refill that buf with t+2
    issue(0, 0);
    issue(1, 1);
    for (int t = 0; t < T; t++) {
        if (t + 1 < T) cp_wait<1>(); else cp_wait<0>();
        __syncthreads();
        compute_slab(Abase(t & 1), Bbase(t & 1));
        __syncthreads();
        if (t + 2 < T) issue(t + 2, t & 1);
    }

    // ---- epilogue ----
    const int gid = lane >> 2, tig = lane & 3;
    #pragma unroll
    for (int mt = 0; mt < 2; mt++) {
        #pragma unroll
        for (int nt = 0; nt < 4; nt++) {
            int cc = cbase + warp_n * 32 + nt * 8 + tig * 2;
            float b0 = bs[cc], b1 = bs[cc + 1];
            int r0 = m0 + warp_m * 32 + mt * 16 + gid;
            if (r0 < M) {
                float2 o = make_float2(c[mt][nt][0] + b0, c[mt][nt][1] + b1);
                if (MODE == 1) {
                    float2 id = *(const float2*)(ident + (size_t)r0 * ldc + cc);
                    o.x += id.x; o.y += id.y;
                    *(float2*)(D0 + (size_t)r0 * ldc + cc) = o;
                } else {
                    __half2 oh = __floats2half2_rn(o.x, o.y);
                    *(uint32_t*)(dsth + (size_t)r0 * ldc + cc) = *(uint32_t*)&oh;
                }
            }
            int r1 = r0 + 8;
            if (r1 < M) {
                float2 o = make_float2(c[mt][nt][2] + b0, c[mt][nt][3] + b1);
                if (MODE == 1) {
                    float2 id = *(const float2*)(ident + (size_t)r1 * ldc + cc);
                    o.x += id.x; o.y += id.y;
                    *(float2*)(D0 + (size_t)r1 * ldc + cc) = o;
                } else {
                    __half2 oh = __floats2half2_rn(o.x, o.y);
                    *(uint32_t*)(dsth + (size_t)r1 * ldc + cc) = *(uint32_t*)&oh;
                }
            }
        }
    }
}

// ----------------------------------------------------------------------------
// Deformable sampling: 32 threads/query (8 heads x 4 groups), 8 channels/thread.
// All inputs fp16 (V, OFF, ATT); fp32 accumulation; fp16 S out.
// ----------------------------------------------------------------------------
__global__ void __launch_bounds__(256) sample_kernel(
    const __half* __restrict__ V, const __half* __restrict__ OFF,
    const __half* __restrict__ ATT, const float* __restrict__ RP)
{
    const int q = blockIdx.x * 8 + (threadIdx.x >> 5);
    if (q >= NQ) return;
    const int lane = threadIdx.x & 31;
    const int h    = lane >> 2;
    const int ch0  = h * 32 + (lane & 3) * 8;

    uint4 attv = *(const uint4*)(ATT + (size_t)q * 64 + h * 8);
    uint4 offv[2];
    offv[0] = *(const uint4*)(OFF + (size_t)q * 128 + h * 16);
    offv[1] = *(const uint4*)(OFF + (size_t)q * 128 + h * 16 + 8);
    const __half2* ap = (const __half2*)&attv;

    float4 acc0 = make_float4(0.f, 0.f, 0.f, 0.f);
    float4 acc1 = make_float4(0.f, 0.f, 0.f, 0.f);
    #pragma unroll
    for (int qu = 0; qu < 2; qu++) {
        float2 a01 = __half22float2(ap[qu * 2 + 0]);
        float2 a23 = __half22float2(ap[qu * 2 + 1]);
        float l0 = a01.x, l1 = a01.y, l2 = a23.x, l3 = a23.y;
        float mx = fmaxf(fmaxf(l0, l1), fmaxf(l2, l3));
        float e0 = __expf(l0 - mx), e1 = __expf(l1 - mx);
        float e2 = __expf(l2 - mx), e3 = __expf(l3 - mx);
        float inv = 1.f / (e0 + e1 + e2 + e3);
        float w[4] = {e0 * inv, e1 * inv, e2 * inv, e3 * inv};

        float rpx = RP[(size_t)qu * NQ * 2 + (size_t)q * 2 + 0];
        float rpy = RP[(size_t)qu * NQ * 2 + (size_t)q * 2 + 1];
        const __half2* op = (const __half2*)&offv[qu];

        #pragma unroll
        for (int p = 0; p < 4; p++) {
            float2 oxy = __half22float2(op[p]);
            float x = (rpx + oxy.x * (1.f / GRID_W)) * GRID_W - 0.5f;
            float y = (rpy + oxy.y * (1.f / GRID_H)) * GRID_H - 0.5f;
            float x0f = floorf(x), y0f = floorf(y);
            float wx = x - x0f, wy = y - y0f;
            int x0 = (int)x0f, y0 = (int)y0f;
            float aw = w[p];
            float tw[4] = {aw * (1.f - wx) * (1.f - wy), aw * wx * (1.f - wy),
                           aw * (1.f - wx) * wy,          aw * wx * wy};
            int xs[4] = {x0, x0 + 1, x0,     x0 + 1};
            int ys[4] = {y0, y0,     y0 + 1, y0 + 1};
            #pragma unroll
            for (int t = 0; t < 4; t++) {
                int xx = xs[t], yy = ys[t];
                if (xx >= 0 && xx < GRID_W && yy >= 0 && yy < GRID_H) {
                    uint4 rv = __ldg((const uint4*)(V +
                        ((size_t)yy * GRID_W + xx) * 256 + ch0));
                    const __half2* hp = (const __half2*)&rv;
                    float2 f0 = __half22float2(hp[0]);
                    float2 f1 = __half22float2(hp[1]);
                    float2 f2 = __half22float2(hp[2]);
                    float2 f3 = __half22float2(hp[3]);
                    float wt = tw[t];
                    acc0.x += f0.x * wt; acc0.y += f0.y * wt;
                    acc0.z += f1.x * wt; acc0.w += f1.y * wt;
                    acc1.x += f2.x * wt; acc1.y += f2.y * wt;
                    acc1.z += f3.x * wt; acc1.w += f3.y * wt;
                }
            }
        }
    }
    acc0.x *= 0.5f; acc0.y *= 0.5f; acc0.z *= 0.5f; acc0.w *= 0.5f;
    acc1.x *= 0.5f; acc1.y *= 0.5f; acc1.z *= 0.5f; acc1.w *= 0.5f;
    __half* Sq = g_S16 + (size_t)q * 256;
    *(uint2*)&Sq[ch0]     = hi4h(acc0);
    *(uint2*)&Sq[ch0 + 4] = hi4h(acc1);
}

// ----------------------------------------------------------------------------
extern "C" void kernel_launch(void* const* d_in, const int* in_sizes, int n_in,
                              void* d_out, int out_size)
{
    const float* query  = (const float*)d_in[0];
    const float* qpos   = (const float*)d_in[1];
    const float* rp     = (const float*)d_in[2];
    const float* W_off  = (const float*)d_in[3];
    const float* b_off  = (const float*)d_in[4];
    const float* W_attn = (const float*)d_in[5];
    const float* b_attn = (const float*)d_in[6];
    const float* W_v    = (const float*)d_in[7];
    const float* b_v    = (const float*)d_in[8];
    const float* W_out  = (const float*)d_in[9];
    const float* b_out  = (const float*)d_in[10];
    float* out = (float*)d_out;

    __half *Aqc, *S16, *V16, *OFF, *ATT, *Wv, *Wcat, *Wout;
    cudaGetSymbolAddress((void**)&Aqc,  g_Aqc);
    cudaGetSymbolAddress((void**)&S16,  g_S16);
    cudaGetSymbolAddress((void**)&V16,  g_V16);
    cudaGetSymbolAddress((void**)&OFF,  g_OFF);
    cudaGetSymbolAddress((void**)&ATT,  g_ATT);
    cudaGetSymbolAddress((void**)&Wv,   g_Wv);
    cudaGetSymbolAddress((void**)&Wcat, g_Wcat);
    cudaGetSymbolAddress((void**)&Wout, g_Wout);

    const int SMEM = 2 * STAGE_BYTES;   // 49152
    cudaFuncSetAttribute(mma_gemm<0>, cudaFuncAttributeMaxDynamicSharedMemorySize, SMEM);
    cudaFuncSetAttribute(mma_gemm<1>, cudaFuncAttributeMaxDynamicSharedMemorySize, SMEM);

    const int MB = (NQ + 127) / 128;  // 176
    dim3 blk(256);

    // splits (weights + qcat) in one launch
    split_all<<<224 + NQ * 64 / 256, blk>>>(query, qpos, W_v, W_off, W_attn, W_out);

    // fused: y0..1 = OFF, y2 = ATT (K=512, heavy-first), y3..6 = value (K=256)
    mma_gemm<0><<<dim3(MB, 7), blk, SMEM>>>(Aqc, 512, Wv, Wcat,
                                            b_v, b_off, b_attn, nullptr,
                                            nullptr, V16, OFF, ATT, NQ);
    // sampling (all fp16 inputs) -> fp16 S
    sample_kernel<<<(NQ + 7) / 8, blk>>>(V16, OFF, ATT, rp);

    // out = S @ W_out + b_out + query  (K=256, fp32 out)
    mma_gemm<1><<<dim3(MB, 4), blk, SMEM>>>(S16, 256, Wout, nullptr,
                                            b_out, nullptr, nullptr, query,
                                            out, nullptr, nullptr, nullptr, NQ);
}